// round 2
// baseline (speedup 1.0000x reference)
#include <cuda_runtime.h>
#include <stdint.h>

#define N_NODES 150000
#define N_EDGES 3000000
#define D 64
#define D2 (D/2)   // float2 elements per row = 32

// ---------- device scratch (no allocations allowed) ----------
__device__ float2 g_sc_a[N_NODES * D2];   // scaled embedding buffer A (x * deg)
__device__ float2 g_sc_b[N_NODES * D2];   // scaled embedding buffer B
__device__ float2 g_acc [N_NODES * D2];   // running sum of layer embeddings
__device__ int    g_cnt [N_NODES];        // in-degree histogram
__device__ int    g_off [N_NODES + 1];    // CSR offsets (by dst)
__device__ int    g_cur [N_NODES];        // scatter cursors
__device__ int    g_srcs[N_EDGES];        // src node ids grouped by dst

// ---------- CSR build ----------
__global__ void k_zero_cnt() {
    int i = blockIdx.x * blockDim.x + threadIdx.x;
    if (i < N_NODES) g_cnt[i] = 0;
}

__global__ void k_hist(const int* __restrict__ dst) {
    int e = blockIdx.x * blockDim.x + threadIdx.x;
    if (e < N_EDGES) atomicAdd(&g_cnt[dst[e]], 1);
}

// single-block exclusive scan over 150K counts (1024 threads, chunked)
__global__ void k_scan() {
    __shared__ int sh[1024];
    __shared__ int carry;
    int t = threadIdx.x;
    if (t == 0) carry = 0;
    __syncthreads();
    for (int base = 0; base < N_NODES; base += 1024) {
        int idx = base + t;
        int v = (idx < N_NODES) ? g_cnt[idx] : 0;
        sh[t] = v;
        __syncthreads();
        #pragma unroll
        for (int of = 1; of < 1024; of <<= 1) {
            int add = (t >= of) ? sh[t - of] : 0;
            __syncthreads();
            sh[t] += add;
            __syncthreads();
        }
        if (idx < N_NODES) {
            int excl = carry + sh[t] - v;
            g_off[idx] = excl;
            g_cur[idx] = excl;
        }
        __syncthreads();
        if (t == 1023) carry += sh[1023];
        __syncthreads();
    }
    if (t == 0) g_off[N_NODES] = carry;
}

__global__ void k_scatter(const int* __restrict__ src, const int* __restrict__ dst) {
    int e = blockIdx.x * blockDim.x + threadIdx.x;
    if (e < N_EDGES) {
        int pos = atomicAdd(&g_cur[dst[e]], 1);
        g_srcs[pos] = src[e];
    }
}

// ---------- node init: acc = emb ; scaled = emb * deg ----------
__global__ void k_init(const float2* __restrict__ emb,
                       const float*  __restrict__ deg) {
    int i = blockIdx.x * blockDim.x + threadIdx.x;   // over N_NODES * D2
    if (i >= N_NODES * D2) return;
    int node = i >> 5;          // i / D2
    float d = deg[node];
    float2 v = emb[i];
    g_acc[i] = v;
    g_sc_a[i] = make_float2(v.x * d, v.y * d);
}

// ---------- SpMM layer: one warp per destination node ----------
// DIR=0: read g_sc_a, write g_sc_b.  DIR=1: read g_sc_b, write g_sc_a.
// v       = deg * sum_{e in CSR(node)} sc_in[src[e]]         (new embedding x)
// acc    += v
// sc_out  = v * deg                                          (input for next layer)
// LAST: out = (acc + v) / 4  (mean over ego + 3 layers)
template <int DIR, int LAST>
__global__ void k_spmm(const float* __restrict__ deg,
                       float2*      __restrict__ out) {
    const float2* __restrict__ sc_in  = (DIR == 0) ? g_sc_a : g_sc_b;
    float2*       __restrict__ sc_out = (DIR == 0) ? g_sc_b : g_sc_a;

    int gid  = blockIdx.x * blockDim.x + threadIdx.x;
    int node = gid >> 5;
    int lane = gid & 31;
    if (node >= N_NODES) return;

    int b = g_off[node];
    int e = g_off[node + 1];

    float sx = 0.f, sy = 0.f;
    int j = b;
    for (; j + 4 <= e; j += 4) {
        int i0 = g_srcs[j + 0];
        int i1 = g_srcs[j + 1];
        int i2 = g_srcs[j + 2];
        int i3 = g_srcs[j + 3];
        float2 a0 = sc_in[(size_t)i0 * D2 + lane];
        float2 a1 = sc_in[(size_t)i1 * D2 + lane];
        float2 a2 = sc_in[(size_t)i2 * D2 + lane];
        float2 a3 = sc_in[(size_t)i3 * D2 + lane];
        sx += (a0.x + a1.x) + (a2.x + a3.x);
        sy += (a0.y + a1.y) + (a2.y + a3.y);
    }
    for (; j < e; ++j) {
        int i0 = g_srcs[j];
        float2 a0 = sc_in[(size_t)i0 * D2 + lane];
        sx += a0.x;
        sy += a0.y;
    }

    float d = deg[node];
    float vx = sx * d, vy = sy * d;          // new embedding x

    size_t o = (size_t)node * D2 + lane;
    float2 a = g_acc[o];
    a.x += vx;
    a.y += vy;

    if (LAST) {
        out[o] = make_float2(a.x * 0.25f, a.y * 0.25f);
    } else {
        g_acc[o] = a;
        sc_out[o] = make_float2(vx * d, vy * d);   // scaled for next layer
    }
}

// ---------- launch (kernel launches ONLY; graph-capturable) ----------
extern "C" void kernel_launch(void* const* d_in, const int* in_sizes, int n_in,
                              void* d_out, int out_size) {
    const float2* emb = (const float2*)d_in[0];
    const float*  deg = (const float*) d_in[1];
    const int*    src = (const int*)   d_in[2];
    const int*    dst = (const int*)   d_in[3];
    float2*       out = (float2*)      d_out;

    const int TB = 256;

    // CSR build (recomputed each launch; deterministic work)
    k_zero_cnt<<<(N_NODES + TB - 1) / TB, TB>>>();
    k_hist    <<<(N_EDGES + TB - 1) / TB, TB>>>(dst);
    k_scan    <<<1, 1024>>>();
    k_scatter <<<(N_EDGES + TB - 1) / TB, TB>>>(src, dst);

    // init: acc = emb, sc_a = emb * deg
    k_init<<<(N_NODES * D2 + TB - 1) / TB, TB>>>(emb, deg);

    // 3 propagation layers (warp per node: 8 warps / 256-thread block)
    int grid = (N_NODES * 32 + TB - 1) / TB;
    k_spmm<0, 0><<<grid, TB>>>(deg, out);   // layer 1: a -> b
    k_spmm<1, 0><<<grid, TB>>>(deg, out);   // layer 2: b -> a
    k_spmm<0, 1><<<grid, TB>>>(deg, out);   // layer 3: a -> out
}

// round 3
// speedup vs baseline: 1.6733x; 1.6733x over previous
#include <cuda_runtime.h>
#include <stdint.h>

#define N_NODES 150000
#define N_EDGES 3000000
#define D 64
#define D2 (D/2)            // float2 per row = 32
#define SCAN_B 1024
#define NB ((N_NODES + SCAN_B - 1) / SCAN_B)   // 147 scan blocks

// ---------- device scratch (no allocations allowed) ----------
__device__ float2 g_sc_a[N_NODES * D2];
__device__ float2 g_sc_b[N_NODES * D2];
__device__ float2 g_acc [N_NODES * D2];
__device__ int    g_cnt [N_NODES];
__device__ int    g_off [N_NODES + 1];
__device__ int    g_cur [N_NODES];
__device__ int    g_srcs[N_EDGES];
__device__ int    g_bsum[NB];      // per-scan-block sums
__device__ int    g_bpre[NB];      // exclusive prefix of block sums

// ---------- init: acc = emb ; sc_a = emb*deg ; zero cnt ----------
__global__ void k_init(const float2* __restrict__ emb,
                       const float*  __restrict__ deg) {
    int i = blockIdx.x * blockDim.x + threadIdx.x;   // over N_NODES * D2
    if (i >= N_NODES * D2) return;
    int node = i >> 5;
    int lane = i & 31;
    float d = deg[node];
    float2 v = emb[i];
    g_acc[i] = v;
    g_sc_a[i] = make_float2(v.x * d, v.y * d);
    if (lane == 0) g_cnt[node] = 0;
}

__global__ void k_hist(const int* __restrict__ dst) {
    int e = blockIdx.x * blockDim.x + threadIdx.x;
    if (e < N_EDGES) atomicAdd(&g_cnt[dst[e]], 1);
}

// ---------- hierarchical scan ----------
// pass 1: per-block (1024) reduction of counts
__global__ void k_bsum() {
    int i = blockIdx.x * SCAN_B + threadIdx.x;
    int v = (i < N_NODES) ? g_cnt[i] : 0;
    #pragma unroll
    for (int of = 16; of > 0; of >>= 1)
        v += __shfl_down_sync(0xffffffffu, v, of);
    __shared__ int ws[32];
    int wid = threadIdx.x >> 5, lane = threadIdx.x & 31;
    if (lane == 0) ws[wid] = v;
    __syncthreads();
    if (wid == 0) {
        v = ws[lane];
        #pragma unroll
        for (int of = 16; of > 0; of >>= 1)
            v += __shfl_down_sync(0xffffffffu, v, of);
        if (lane == 0) g_bsum[blockIdx.x] = v;
    }
}

// pass 2: scan the NB (=147) block sums in one tiny block
__global__ void k_scan_bsum() {
    __shared__ int sh[256];
    int t = threadIdx.x;
    int v = (t < NB) ? g_bsum[t] : 0;
    sh[t] = v;
    __syncthreads();
    #pragma unroll
    for (int of = 1; of < 256; of <<= 1) {
        int add = (t >= of) ? sh[t - of] : 0;
        __syncthreads();
        sh[t] += add;
        __syncthreads();
    }
    if (t < NB) g_bpre[t] = sh[t] - v;        // exclusive
    if (t == NB - 1) g_off[N_NODES] = sh[t];  // total
}

// pass 3: per-block exclusive scan + block prefix -> offsets & cursors
__global__ void k_offsets() {
    int i = blockIdx.x * SCAN_B + threadIdx.x;
    int v = (i < N_NODES) ? g_cnt[i] : 0;
    int wid = threadIdx.x >> 5, lane = threadIdx.x & 31;

    // warp inclusive scan
    int incl = v;
    #pragma unroll
    for (int of = 1; of < 32; of <<= 1) {
        int n = __shfl_up_sync(0xffffffffu, incl, of);
        if (lane >= of) incl += n;
    }
    __shared__ int ws[32];
    if (lane == 31) ws[wid] = incl;
    __syncthreads();
    if (wid == 0) {
        int s = ws[lane];
        #pragma unroll
        for (int of = 1; of < 32; of <<= 1) {
            int n = __shfl_up_sync(0xffffffffu, s, of);
            if (lane >= of) s += n;
        }
        ws[lane] = s;
    }
    __syncthreads();
    int warp_pre = (wid > 0) ? ws[wid - 1] : 0;
    int excl = g_bpre[blockIdx.x] + warp_pre + incl - v;
    if (i < N_NODES) { g_off[i] = excl; g_cur[i] = excl; }
}

__global__ void k_scatter(const int* __restrict__ src, const int* __restrict__ dst) {
    int e = blockIdx.x * blockDim.x + threadIdx.x;
    if (e < N_EDGES) {
        int pos = atomicAdd(&g_cur[dst[e]], 1);
        g_srcs[pos] = src[e];
    }
}

// ---------- SpMM layer: one warp per destination node ----------
template <int DIR, int LAST>
__global__ void k_spmm(const float* __restrict__ deg,
                       float2*      __restrict__ out) {
    const float2* __restrict__ sc_in  = (DIR == 0) ? g_sc_a : g_sc_b;
    float2*       __restrict__ sc_out = (DIR == 0) ? g_sc_b : g_sc_a;

    int gid  = blockIdx.x * blockDim.x + threadIdx.x;
    int node = gid >> 5;
    int lane = gid & 31;
    if (node >= N_NODES) return;

    int b = g_off[node];
    int e = g_off[node + 1];

    float sx = 0.f, sy = 0.f;
    int j = b;
    for (; j + 4 <= e; j += 4) {
        int i0 = g_srcs[j + 0];
        int i1 = g_srcs[j + 1];
        int i2 = g_srcs[j + 2];
        int i3 = g_srcs[j + 3];
        float2 a0 = sc_in[(size_t)i0 * D2 + lane];
        float2 a1 = sc_in[(size_t)i1 * D2 + lane];
        float2 a2 = sc_in[(size_t)i2 * D2 + lane];
        float2 a3 = sc_in[(size_t)i3 * D2 + lane];
        sx += (a0.x + a1.x) + (a2.x + a3.x);
        sy += (a0.y + a1.y) + (a2.y + a3.y);
    }
    for (; j < e; ++j) {
        int i0 = g_srcs[j];
        float2 a0 = sc_in[(size_t)i0 * D2 + lane];
        sx += a0.x;
        sy += a0.y;
    }

    float d = deg[node];
    float vx = sx * d, vy = sy * d;

    size_t o = (size_t)node * D2 + lane;
    float2 a = g_acc[o];
    a.x += vx;
    a.y += vy;

    if (LAST) {
        out[o] = make_float2(a.x * 0.25f, a.y * 0.25f);
    } else {
        g_acc[o] = a;
        sc_out[o] = make_float2(vx * d, vy * d);
    }
}

// ---------- launch ----------
extern "C" void kernel_launch(void* const* d_in, const int* in_sizes, int n_in,
                              void* d_out, int out_size) {
    const float2* emb = (const float2*)d_in[0];
    const float*  deg = (const float*) d_in[1];
    const int*    src = (const int*)   d_in[2];
    const int*    dst = (const int*)   d_in[3];
    float2*       out = (float2*)      d_out;

    const int TB = 256;

    k_init<<<(N_NODES * D2 + TB - 1) / TB, TB>>>(emb, deg);   // also zeroes cnt
    k_hist<<<(N_EDGES + TB - 1) / TB, TB>>>(dst);
    k_bsum<<<NB, SCAN_B>>>();
    k_scan_bsum<<<1, 256>>>();
    k_offsets<<<NB, SCAN_B>>>();
    k_scatter<<<(N_EDGES + TB - 1) / TB, TB>>>(src, dst);

    int grid = (N_NODES * 32 + TB - 1) / TB;
    k_spmm<0, 0><<<grid, TB>>>(deg, out);   // layer 1: a -> b
    k_spmm<1, 0><<<grid, TB>>>(deg, out);   // layer 2: b -> a
    k_spmm<0, 1><<<grid, TB>>>(deg, out);   // layer 3: a -> out
}

// round 4
// speedup vs baseline: 1.6959x; 1.0135x over previous
#include <cuda_runtime.h>
#include <cuda_fp16.h>
#include <stdint.h>

#define N_NODES 150000
#define N_EDGES 3000000
#define D 64
#define D2 (D/2)            // 32 lanes; fp32 acc rows are float2, sc rows are half2
#define SCAN_B 1024
#define NB ((N_NODES + SCAN_B - 1) / SCAN_B)   // 147 scan blocks

// ---------- device scratch (no allocations allowed) ----------
__device__ __half2 g_sc_a[N_NODES * D2];   // scaled embedding (x * deg), fp16
__device__ __half2 g_sc_b[N_NODES * D2];
__device__ float2  g_acc [N_NODES * D2];   // running layer sum, fp32
__device__ int     g_cnt [N_NODES];
__device__ int     g_off [N_NODES + 1];
__device__ int     g_cur [N_NODES];
__device__ int     g_srcs[N_EDGES];
__device__ int     g_bsum[NB];
__device__ int     g_bpre[NB];

// ---------- init: acc = emb ; sc_a = half(emb*deg) ; zero cnt ----------
__global__ void k_init(const float2* __restrict__ emb,
                       const float*  __restrict__ deg) {
    int i = blockIdx.x * blockDim.x + threadIdx.x;   // over N_NODES * D2
    if (i >= N_NODES * D2) return;
    int node = i >> 5;
    int lane = i & 31;
    float d = deg[node];
    float2 v = emb[i];
    g_acc[i] = v;
    g_sc_a[i] = __floats2half2_rn(v.x * d, v.y * d);
    if (lane == 0) g_cnt[node] = 0;
}

__global__ void k_hist(const int* __restrict__ dst) {
    int e = blockIdx.x * blockDim.x + threadIdx.x;
    if (e < N_EDGES) atomicAdd(&g_cnt[dst[e]], 1);
}

// ---------- hierarchical scan ----------
__global__ void k_bsum() {
    int i = blockIdx.x * SCAN_B + threadIdx.x;
    int v = (i < N_NODES) ? g_cnt[i] : 0;
    #pragma unroll
    for (int of = 16; of > 0; of >>= 1)
        v += __shfl_down_sync(0xffffffffu, v, of);
    __shared__ int ws[32];
    int wid = threadIdx.x >> 5, lane = threadIdx.x & 31;
    if (lane == 0) ws[wid] = v;
    __syncthreads();
    if (wid == 0) {
        v = ws[lane];
        #pragma unroll
        for (int of = 16; of > 0; of >>= 1)
            v += __shfl_down_sync(0xffffffffu, v, of);
        if (lane == 0) g_bsum[blockIdx.x] = v;
    }
}

__global__ void k_scan_bsum() {
    __shared__ int sh[256];
    int t = threadIdx.x;
    int v = (t < NB) ? g_bsum[t] : 0;
    sh[t] = v;
    __syncthreads();
    #pragma unroll
    for (int of = 1; of < 256; of <<= 1) {
        int add = (t >= of) ? sh[t - of] : 0;
        __syncthreads();
        sh[t] += add;
        __syncthreads();
    }
    if (t < NB) g_bpre[t] = sh[t] - v;
    if (t == NB - 1) g_off[N_NODES] = sh[t];
}

__global__ void k_offsets() {
    int i = blockIdx.x * SCAN_B + threadIdx.x;
    int v = (i < N_NODES) ? g_cnt[i] : 0;
    int wid = threadIdx.x >> 5, lane = threadIdx.x & 31;

    int incl = v;
    #pragma unroll
    for (int of = 1; of < 32; of <<= 1) {
        int n = __shfl_up_sync(0xffffffffu, incl, of);
        if (lane >= of) incl += n;
    }
    __shared__ int ws[32];
    if (lane == 31) ws[wid] = incl;
    __syncthreads();
    if (wid == 0) {
        int s = ws[lane];
        #pragma unroll
        for (int of = 1; of < 32; of <<= 1) {
            int n = __shfl_up_sync(0xffffffffu, s, of);
            if (lane >= of) s += n;
        }
        ws[lane] = s;
    }
    __syncthreads();
    int warp_pre = (wid > 0) ? ws[wid - 1] : 0;
    int excl = g_bpre[blockIdx.x] + warp_pre + incl - v;
    if (i < N_NODES) { g_off[i] = excl; g_cur[i] = excl; }
}

__global__ void k_scatter(const int* __restrict__ src, const int* __restrict__ dst) {
    int e = blockIdx.x * blockDim.x + threadIdx.x;
    if (e < N_EDGES) {
        int pos = atomicAdd(&g_cur[dst[e]], 1);
        g_srcs[pos] = src[e];
    }
}

// ---------- SpMM layer: one warp per destination node, fp16 gather ----------
template <int DIR, int LAST>
__global__ void k_spmm(const float* __restrict__ deg,
                       float2*      __restrict__ out) {
    const __half2* __restrict__ sc_in  = (DIR == 0) ? g_sc_a : g_sc_b;
    __half2*       __restrict__ sc_out = (DIR == 0) ? g_sc_b : g_sc_a;

    int gid  = blockIdx.x * blockDim.x + threadIdx.x;
    int node = gid >> 5;
    int lane = gid & 31;
    if (node >= N_NODES) return;

    int b = g_off[node];
    int e = g_off[node + 1];

    float sx = 0.f, sy = 0.f;
    int j = b;
    // 8-wide unroll: 8 independent 128B row loads in flight per warp
    for (; j + 8 <= e; j += 8) {
        float2 f[8];
        #pragma unroll
        for (int u = 0; u < 8; u++) {
            int s = g_srcs[j + u];
            f[u] = __half22float2(sc_in[(size_t)s * D2 + lane]);
        }
        #pragma unroll
        for (int u = 0; u < 8; u++) { sx += f[u].x; sy += f[u].y; }
    }
    for (; j + 4 <= e; j += 4) {
        float2 f[4];
        #pragma unroll
        for (int u = 0; u < 4; u++) {
            int s = g_srcs[j + u];
            f[u] = __half22float2(sc_in[(size_t)s * D2 + lane]);
        }
        #pragma unroll
        for (int u = 0; u < 4; u++) { sx += f[u].x; sy += f[u].y; }
    }
    for (; j < e; ++j) {
        float2 f = __half22float2(sc_in[(size_t)g_srcs[j] * D2 + lane]);
        sx += f.x; sy += f.y;
    }

    float d = deg[node];
    float vx = sx * d, vy = sy * d;          // new embedding x

    size_t o = (size_t)node * D2 + lane;
    float2 a = g_acc[o];
    a.x += vx;
    a.y += vy;

    if (LAST) {
        out[o] = make_float2(a.x * 0.25f, a.y * 0.25f);
    } else {
        g_acc[o] = a;
        sc_out[o] = __floats2half2_rn(vx * d, vy * d);
    }
}

// ---------- launch ----------
extern "C" void kernel_launch(void* const* d_in, const int* in_sizes, int n_in,
                              void* d_out, int out_size) {
    const float2* emb = (const float2*)d_in[0];
    const float*  deg = (const float*) d_in[1];
    const int*    src = (const int*)   d_in[2];
    const int*    dst = (const int*)   d_in[3];
    float2*       out = (float2*)      d_out;

    const int TB = 256;

    k_init<<<(N_NODES * D2 + TB - 1) / TB, TB>>>(emb, deg);
    k_hist<<<(N_EDGES + TB - 1) / TB, TB>>>(dst);
    k_bsum<<<NB, SCAN_B>>>();
    k_scan_bsum<<<1, 256>>>();
    k_offsets<<<NB, SCAN_B>>>();
    k_scatter<<<(N_EDGES + TB - 1) / TB, TB>>>(src, dst);

    int grid = (N_NODES * 32 + TB - 1) / TB;
    k_spmm<0, 0><<<grid, TB>>>(deg, out);   // layer 1: a -> b
    k_spmm<1, 0><<<grid, TB>>>(deg, out);   // layer 2: b -> a
    k_spmm<0, 1><<<grid, TB>>>(deg, out);   // layer 3: a -> out
}

// round 6
// speedup vs baseline: 1.7193x; 1.0138x over previous
#include <cuda_runtime.h>
#include <cuda_fp16.h>
#include <stdint.h>

#define N_NODES 150000
#define N_EDGES 3000000
#define D 64
#define D2 (D/2)            // 32 float2 / half2 columns per row
#define ROW_I4 8            // fp16 row = 64 halfs = 128B = 8 int4
#define SCAN_B 1024
#define NB ((N_NODES + SCAN_B - 1) / SCAN_B)   // 147 scan blocks

// ---------- device scratch (no allocations allowed) ----------
__device__ __half2 g_sc_a[N_NODES * D2];   // scaled embedding (x * deg), fp16
__device__ __half2 g_sc_b[N_NODES * D2];
__device__ float2  g_acc [N_NODES * D2];   // running layer sum, fp32
__device__ int     g_cnt [N_NODES];
__device__ int     g_off [N_NODES + 1];
__device__ int     g_cur [N_NODES];
__device__ int     g_srcs[N_EDGES];
__device__ int     g_bsum[NB];
__device__ int     g_bpre[NB];

// ---------- init: acc = emb ; sc_a = half(emb*deg) ; zero cnt ----------
__global__ void k_init(const float2* __restrict__ emb,
                       const float*  __restrict__ deg) {
    int i = blockIdx.x * blockDim.x + threadIdx.x;   // over N_NODES * D2
    if (i >= N_NODES * D2) return;
    int node = i >> 5;
    int lane = i & 31;
    float d = deg[node];
    float2 v = emb[i];
    g_acc[i] = v;
    g_sc_a[i] = __floats2half2_rn(v.x * d, v.y * d);
    if (lane == 0) g_cnt[node] = 0;
}

__global__ void k_hist(const int* __restrict__ dst) {
    int e = blockIdx.x * blockDim.x + threadIdx.x;
    if (e < N_EDGES) atomicAdd(&g_cnt[dst[e]], 1);
}

// ---------- hierarchical scan ----------
__global__ void k_bsum() {
    int i = blockIdx.x * SCAN_B + threadIdx.x;
    int v = (i < N_NODES) ? g_cnt[i] : 0;
    #pragma unroll
    for (int of = 16; of > 0; of >>= 1)
        v += __shfl_down_sync(0xffffffffu, v, of);
    __shared__ int ws[32];
    int wid = threadIdx.x >> 5, lane = threadIdx.x & 31;
    if (lane == 0) ws[wid] = v;
    __syncthreads();
    if (wid == 0) {
        v = ws[lane];
        #pragma unroll
        for (int of = 16; of > 0; of >>= 1)
            v += __shfl_down_sync(0xffffffffu, v, of);
        if (lane == 0) g_bsum[blockIdx.x] = v;
    }
}

__global__ void k_scan_bsum() {
    __shared__ int sh[256];
    int t = threadIdx.x;
    int v = (t < NB) ? g_bsum[t] : 0;
    sh[t] = v;
    __syncthreads();
    #pragma unroll
    for (int of = 1; of < 256; of <<= 1) {
        int add = (t >= of) ? sh[t - of] : 0;
        __syncthreads();
        sh[t] += add;
        __syncthreads();
    }
    if (t < NB) g_bpre[t] = sh[t] - v;
    if (t == NB - 1) g_off[N_NODES] = sh[t];
}

__global__ void k_offsets() {
    int i = blockIdx.x * SCAN_B + threadIdx.x;
    int v = (i < N_NODES) ? g_cnt[i] : 0;
    int wid = threadIdx.x >> 5, lane = threadIdx.x & 31;

    int incl = v;
    #pragma unroll
    for (int of = 1; of < 32; of <<= 1) {
        int n = __shfl_up_sync(0xffffffffu, incl, of);
        if (lane >= of) incl += n;
    }
    __shared__ int ws[32];
    if (lane == 31) ws[wid] = incl;
    __syncthreads();
    if (wid == 0) {
        int s = ws[lane];
        #pragma unroll
        for (int of = 1; of < 32; of <<= 1) {
            int n = __shfl_up_sync(0xffffffffu, s, of);
            if (lane >= of) s += n;
        }
        ws[lane] = s;
    }
    __syncthreads();
    int warp_pre = (wid > 0) ? ws[wid - 1] : 0;
    int excl = g_bpre[blockIdx.x] + warp_pre + incl - v;
    if (i < N_NODES) { g_off[i] = excl; g_cur[i] = excl; }
}

__global__ void k_scatter(const int* __restrict__ src, const int* __restrict__ dst) {
    int e = blockIdx.x * blockDim.x + threadIdx.x;
    if (e < N_EDGES) {
        int pos = atomicAdd(&g_cur[dst[e]], 1);
        g_srcs[pos] = src[e];
    }
}

// ---------- SpMM layer: warp per dst node, 4 edges per warp-wide LDG.128 ----------
// lane = 8*g + s: subgroup g in [0,4) handles edge chunk element g,
// segment s in [0,8) covers 16B (4 half2 = float2-columns 4s..4s+3) of the row.
template <int DIR, int LAST>
__global__ void k_spmm(const float* __restrict__ deg,
                       float2*      __restrict__ out) {
    const int4* __restrict__ sc_in =
        (const int4*)((DIR == 0) ? (const void*)g_sc_a : (const void*)g_sc_b);
    __half2*    __restrict__ sc_out = (DIR == 0) ? g_sc_b : g_sc_a;

    int gid  = blockIdx.x * blockDim.x + threadIdx.x;
    int node = gid >> 5;
    int lane = gid & 31;
    if (node >= N_NODES) return;
    int g = lane >> 3;          // edge subgroup 0..3
    int s = lane & 7;           // 16B segment 0..7

    int b = g_off[node];
    int e = g_off[node + 1];

    float2 acc[4];
    #pragma unroll
    for (int k = 0; k < 4; k++) acc[k] = make_float2(0.f, 0.f);

    const int4 z4 = make_int4(0, 0, 0, 0);
    // 8 edges per iteration: two independent 16B loads per lane in flight
    for (int j = b; j < e; j += 8) {
        int j0 = j + g;
        int j1 = j + 4 + g;
        int4 v0 = z4, v1 = z4;
        if (j0 < e) v0 = sc_in[(size_t)g_srcs[j0] * ROW_I4 + s];
        if (j1 < e) v1 = sc_in[(size_t)g_srcs[j1] * ROW_I4 + s];

        const unsigned* w0 = (const unsigned*)&v0;
        const unsigned* w1 = (const unsigned*)&v1;
        #pragma unroll
        for (int k = 0; k < 4; k++) {
            float2 f0 = __half22float2(*(const __half2*)&w0[k]);
            float2 f1 = __half22float2(*(const __half2*)&w1[k]);
            acc[k].x += f0.x + f1.x;
            acc[k].y += f0.y + f1.y;
        }
    }

    // reduce across the 4 subgroups (butterfly over lane bits 3,4)
    #pragma unroll
    for (int k = 0; k < 4; k++) {
        acc[k].x += __shfl_xor_sync(0xffffffffu, acc[k].x, 8);
        acc[k].y += __shfl_xor_sync(0xffffffffu, acc[k].y, 8);
        acc[k].x += __shfl_xor_sync(0xffffffffu, acc[k].x, 16);
        acc[k].y += __shfl_xor_sync(0xffffffffu, acc[k].y, 16);
    }

    // epilogue: lane (g,s) owns float2-column c = 4*s + g with value acc[g]
    float d = deg[node];
    int   c = (s << 2) + g;
    float vx = acc[g].x * d, vy = acc[g].y * d;

    size_t o = (size_t)node * D2 + c;
    float2 a = g_acc[o];
    a.x += vx;
    a.y += vy;

    if (LAST) {
        out[o] = make_float2(a.x * 0.25f, a.y * 0.25f);
    } else {
        g_acc[o] = a;
        sc_out[o] = __floats2half2_rn(vx * d, vy * d);
    }
}

// ---------- launch ----------
extern "C" void kernel_launch(void* const* d_in, const int* in_sizes, int n_in,
                              void* d_out, int out_size) {
    const float2* emb = (const float2*)d_in[0];
    const float*  deg = (const float*) d_in[1];
    const int*    src = (const int*)   d_in[2];
    const int*    dst = (const int*)   d_in[3];
    float2*       out = (float2*)      d_out;

    const int TB = 256;

    k_init<<<(N_NODES * D2 + TB - 1) / TB, TB>>>(emb, deg);
    k_hist<<<(N_EDGES + TB - 1) / TB, TB>>>(dst);
    k_bsum<<<NB, SCAN_B>>>();
    k_scan_bsum<<<1, 256>>>();
    k_offsets<<<NB, SCAN_B>>>();
    k_scatter<<<(N_EDGES + TB - 1) / TB, TB>>>(src, dst);

    int grid = (N_NODES * 32 + TB - 1) / TB;
    k_spmm<0, 0><<<grid, TB>>>(deg, out);   // layer 1: a -> b
    k_spmm<1, 0><<<grid, TB>>>(deg, out);   // layer 2: b -> a
    k_spmm<0, 1><<<grid, TB>>>(deg, out);   // layer 3: a -> out
}

// round 7
// speedup vs baseline: 1.8722x; 1.0889x over previous
#include <cuda_runtime.h>
#include <cuda_fp16.h>
#include <stdint.h>

#define N_NODES 150000
#define N_EDGES 3000000
#define D 64
#define D2 (D/2)            // 32 half2/float2 columns per row
#define ROW_I4 8            // fp16 row = 64 halfs = 128B = 8 int4
#define SCAN_B 1024
#define NB ((N_NODES + SCAN_B - 1) / SCAN_B)   // 147 scan blocks

// ---------- device scratch (no allocations allowed) ----------
__device__ __half2 g_sc_a[N_NODES * D2];   // scaled embedding (x * deg), fp16
__device__ __half2 g_sc_b[N_NODES * D2];
__device__ float2  g_acc [N_NODES * D2];   // running layer sum, fp32
__device__ int     g_cnt [N_NODES];        // zero at entry (static init / re-zeroed by spmm3)
__device__ int     g_off [N_NODES + 1];
__device__ int     g_cur [N_NODES];
__device__ int     g_srcs[N_EDGES];
__device__ unsigned long long g_pstate[NB]; // lookback: (sum<<32)|flag; 0=invalid,1=partial,2=prefix

// ---------- launch 0: init (acc=emb, sc_a=half(emb*deg)) + hist + reset lookback ----------
__global__ void k_init_hist(const float2* __restrict__ emb,
                            const float*  __restrict__ deg,
                            const int*    __restrict__ dst) {
    int i = blockIdx.x * blockDim.x + threadIdx.x;
    if (i < N_NODES * D2) {
        int node = i >> 5;
        float d = deg[node];
        float2 v = __ldcs(&emb[i]);          // streamed once
        __stcs(&g_acc[i], v);                // streaming: keep out of L2 hot set
        g_sc_a[i] = __floats2half2_rn(v.x * d, v.y * d);  // hot: default policy
    }
    if (i < N_EDGES) atomicAdd(&g_cnt[dst[i]], 1);
    if (i < NB) g_pstate[i] = 0ULL;
}

// ---------- launch 1: single-pass decoupled-lookback scan -> offsets & cursors ----------
__global__ void k_scan() {
    int b = blockIdx.x, t = threadIdx.x;
    int i = b * SCAN_B + t;
    int v = (i < N_NODES) ? g_cnt[i] : 0;
    int lane = t & 31, wid = t >> 5;

    // block inclusive scan
    int incl = v;
    #pragma unroll
    for (int of = 1; of < 32; of <<= 1) {
        int n = __shfl_up_sync(0xffffffffu, incl, of);
        if (lane >= of) incl += n;
    }
    __shared__ int ws[32];
    if (lane == 31) ws[wid] = incl;
    __syncthreads();
    if (wid == 0) {
        int s = ws[lane];
        #pragma unroll
        for (int of = 1; of < 32; of <<= 1) {
            int n = __shfl_up_sync(0xffffffffu, s, of);
            if (lane >= of) s += n;
        }
        ws[lane] = s;
    }
    __syncthreads();
    int block_incl = incl + (wid ? ws[wid - 1] : 0);
    int total = ws[31];

    __shared__ int s_base;
    if (t == 0) {
        if (b == 0) {
            atomicExch(&g_pstate[0], ((unsigned long long)(unsigned)total << 32) | 2ULL);
            s_base = 0;
        } else {
            atomicExch(&g_pstate[b], ((unsigned long long)(unsigned)total << 32) | 1ULL);
            int running = 0;
            for (int p = b - 1; p >= 0; ) {
                unsigned long long st;
                do { st = atomicAdd(&g_pstate[p], 0ULL); } while ((st & 3ULL) == 0ULL);
                running += (int)(unsigned)(st >> 32);
                if ((st & 3ULL) == 2ULL) break;
                p--;
            }
            atomicExch(&g_pstate[b],
                ((unsigned long long)(unsigned)(running + total) << 32) | 2ULL);
            s_base = running;
        }
    }
    __syncthreads();
    int excl = s_base + block_incl - v;
    if (i < N_NODES) { g_off[i] = excl; g_cur[i] = excl; }
    if (i == N_NODES - 1) g_off[N_NODES] = excl + v;
}

// ---------- launch 2: scatter src ids into CSR ----------
__global__ void k_scatter(const int* __restrict__ src, const int* __restrict__ dst) {
    int e = blockIdx.x * blockDim.x + threadIdx.x;
    if (e < N_EDGES) {
        int pos = atomicAdd(&g_cur[dst[e]], 1);
        g_srcs[pos] = src[e];
    }
}

// ---------- launches 3-5: SpMM layer, warp per dst node, 4 edges per warp LDG.128 ----------
// lane = 8*g + s: subgroup g in [0,4) handles edge g of each 4-chunk,
// segment s in [0,8) covers 16B (4 half2 = float2-cols 4s..4s+3) of the row.
template <int DIR, int LAST>
__global__ void k_spmm(const float* __restrict__ deg,
                       float2*      __restrict__ out) {
    const int4* __restrict__ sc_in =
        (const int4*)((DIR == 0) ? (const void*)g_sc_a : (const void*)g_sc_b);
    __half2*    __restrict__ sc_out = (DIR == 0) ? g_sc_b : g_sc_a;

    int gid  = blockIdx.x * blockDim.x + threadIdx.x;
    int node = gid >> 5;
    int lane = gid & 31;
    if (node >= N_NODES) return;
    int g = lane >> 3;          // edge subgroup 0..3
    int s = lane & 7;           // 16B segment 0..7

    int b = g_off[node];
    int e = g_off[node + 1];

    float2 acc[4];
    #pragma unroll
    for (int k = 0; k < 4; k++) acc[k] = make_float2(0.f, 0.f);

    const int4 z4 = make_int4(0, 0, 0, 0);
    for (int j = b; j < e; j += 8) {
        int j0 = j + g;
        int j1 = j + 4 + g;
        int4 v0 = z4, v1 = z4;
        if (j0 < e) v0 = sc_in[(size_t)g_srcs[j0] * ROW_I4 + s];
        if (j1 < e) v1 = sc_in[(size_t)g_srcs[j1] * ROW_I4 + s];

        const unsigned* w0 = (const unsigned*)&v0;
        const unsigned* w1 = (const unsigned*)&v1;
        #pragma unroll
        for (int k = 0; k < 4; k++) {
            float2 f0 = __half22float2(*(const __half2*)&w0[k]);
            float2 f1 = __half22float2(*(const __half2*)&w1[k]);
            acc[k].x += f0.x + f1.x;
            acc[k].y += f0.y + f1.y;
        }
    }

    // reduce across the 4 subgroups (butterfly over lane bits 3,4)
    #pragma unroll
    for (int k = 0; k < 4; k++) {
        acc[k].x += __shfl_xor_sync(0xffffffffu, acc[k].x, 8);
        acc[k].y += __shfl_xor_sync(0xffffffffu, acc[k].y, 8);
        acc[k].x += __shfl_xor_sync(0xffffffffu, acc[k].x, 16);
        acc[k].y += __shfl_xor_sync(0xffffffffu, acc[k].y, 16);
    }

    // epilogue: lane (g,s) owns float2-column c = 4*s + g with value acc[g]
    float d = deg[node];
    int   c = (s << 2) + g;
    float vx = acc[g].x * d, vy = acc[g].y * d;

    size_t o = (size_t)node * D2 + c;
    float2 a = __ldcs(&g_acc[o]);        // streaming RMW: keep out of L2 hot set
    a.x += vx;
    a.y += vy;

    if (LAST) {
        __stcs(&out[o], make_float2(a.x * 0.25f, a.y * 0.25f));
        if (lane == 0) g_cnt[node] = 0;  // reset histogram for next graph replay
    } else {
        __stcs(&g_acc[o], a);
        sc_out[o] = __floats2half2_rn(vx * d, vy * d);  // hot: default policy
    }
}

// ---------- launch ----------
extern "C" void kernel_launch(void* const* d_in, const int* in_sizes, int n_in,
                              void* d_out, int out_size) {
    const float2* emb = (const float2*)d_in[0];
    const float*  deg = (const float*) d_in[1];
    const int*    src = (const int*)   d_in[2];
    const int*    dst = (const int*)   d_in[3];
    float2*       out = (float2*)      d_out;

    const int TB = 256;

    k_init_hist<<<(N_NODES * D2 + TB - 1) / TB, TB>>>(emb, deg, dst);  // idx 0
    k_scan<<<NB, SCAN_B>>>();                                          // idx 1
    k_scatter<<<(N_EDGES + TB - 1) / TB, TB>>>(src, dst);              // idx 2

    int grid = (N_NODES * 32 + TB - 1) / TB;
    k_spmm<0, 0><<<grid, TB>>>(deg, out);   // idx 3  <- ncu capture slot
    k_spmm<1, 0><<<grid, TB>>>(deg, out);   // idx 4
    k_spmm<0, 1><<<grid, TB>>>(deg, out);   // idx 5
}